// round 5
// baseline (speedup 1.0000x reference)
#include <cuda_runtime.h>
#include <math.h>

#define BSZ 4096
#define PPTS 64
#define DD 128
#define KCODES 2048
#define HH 256
#define LLAY 5
#define SSTG 4
#define LH 1280   // LLAY*HH

// -------- device scratch (static; no allocation) --------
__device__ float g_zq[BSZ * DD];          // 2 MB  z_q_sum per image
__device__ float g_bet[BSZ * LH];         // 21 MB betas, layout [b][l*256+h]
__device__ float g_e2[SSTG * KCODES];     // ||emb||^2
__device__ float g_lpart[256];            // per-block VQ loss partials

typedef unsigned long long ull;
__device__ __forceinline__ ull pk2(float x, float y) {
    ull r; asm("mov.b64 %0,{%1,%2};" : "=l"(r) : "f"(x), "f"(y)); return r;
}
__device__ __forceinline__ void upk2(ull v, float& x, float& y) {
    asm("mov.b64 {%0,%1},%2;" : "=f"(x), "=f"(y) : "l"(v));
}
__device__ __forceinline__ void fma2(ull& d, ull a, ull b) {
    asm("fma.rn.f32x2 %0,%1,%2,%0;" : "+l"(d) : "l"(a), "l"(b));
}
__device__ __forceinline__ float dot4(float4 a, float4 b) {
    return fmaf(a.x, b.x, fmaf(a.y, b.y, fmaf(a.z, b.z, a.w * b.w)));
}
__device__ __forceinline__ float4 f4add(float4 a, float4 b) {
    return make_float4(a.x + b.x, a.y + b.y, a.z + b.z, a.w + b.w);
}
__device__ __forceinline__ float4 f4sub(float4 a, float4 b) {
    return make_float4(a.x - b.x, a.y - b.y, a.z - b.z, a.w - b.w);
}

// -------- kernel 1: per-code ||e||^2 --------
__global__ void k_e2(const float* __restrict__ emb) {
    int c = blockIdx.x * 256 + threadIdx.x;            // 0..8191
    const float4* row = (const float4*)(emb + (size_t)c * DD);
    float s = 0.f;
#pragma unroll 8
    for (int i = 0; i < 32; ++i) {
        float4 v = row[i];
        s += v.x * v.x + v.y * v.y + v.z * v.z + v.w * v.w;
    }
    g_e2[c] = s;
}

// -------- kernel 2: residual VQ (argmin + z_q_sum + commit loss) --------
// 16 images/block; warp bp owns images (2bp, 2bp+1); lane cl scores codes
// cl and cl+32 of each 64-code tile against both images (2x2 reg blocking).
__global__ __launch_bounds__(256) void k_vq(
    const int* __restrict__ li, const float* __restrict__ lat,
    const float* __restrict__ emb)
{
    __shared__ float4 zc4[16 * 32];      // [b][k4]
    __shared__ float4 em4[64 * 33];      // [code][k4], odd stride: conflict-free
    __shared__ float  e2s[64];
    __shared__ int    win[16];
    __shared__ float  lred[8];

    const int t = threadIdx.x, bp = t >> 5, cl = t & 31;
    const int b0 = 2 * bp, b1 = b0 + 1;
    const int B0 = blockIdx.x * 16;
    const int l0 = li[B0 + b0], l1 = li[B0 + b1];

    float4 r0 = make_float4(0, 0, 0, 0), r1 = r0, q0 = r0, q1 = r0;
    float loss = 0.f;

    for (int s = 0; s < SSTG; ++s) {
        float4 z0 = *(const float4*)&lat[((size_t)l0 * SSTG + s) * DD + cl * 4];
        float4 z1 = *(const float4*)&lat[((size_t)l1 * SSTG + s) * DD + cl * 4];
        r0 = f4add(r0, z0); r1 = f4add(r1, z1);
        float4 ca = f4sub(r0, q0), cb = f4sub(r1, q1);
        zc4[b0 * 32 + cl] = ca;
        zc4[b1 * 32 + cl] = cb;

        float bd0 = 3.4e38f, bd1 = 3.4e38f;
        int bi0 = 0, bi1 = 0;

        for (int tb = 0; tb < KCODES; tb += 64) {
            __syncthreads();   // prev tile consumed; zc4 visible on first tile
#pragma unroll
            for (int i = 0; i < 8; ++i) {
                int lin = t + 256 * i;
                int c = lin >> 5, k4 = lin & 31;
                em4[c * 33 + k4] =
                    *(const float4*)&emb[((size_t)s * KCODES + tb + c) * DD + k4 * 4];
            }
            if (t < 64) e2s[t] = g_e2[s * KCODES + tb + t];
            __syncthreads();

            float a00 = 0, a01 = 0, a10 = 0, a11 = 0;
#pragma unroll 4
            for (int k4 = 0; k4 < 32; ++k4) {
                float4 za = zc4[b0 * 32 + k4];
                float4 zb = zc4[b1 * 32 + k4];
                float4 e0 = em4[cl * 33 + k4];
                float4 e1 = em4[(cl + 32) * 33 + k4];
                a00 += dot4(e0, za); a01 += dot4(e0, zb);
                a10 += dot4(e1, za); a11 += dot4(e1, zb);
            }
            // ascending index visit + strict '<' => first-occurrence argmin
            float d;
            d = fmaf(-2.f, a00, e2s[cl]);      if (d < bd0) { bd0 = d; bi0 = tb + cl; }
            d = fmaf(-2.f, a10, e2s[cl + 32]); if (d < bd0) { bd0 = d; bi0 = tb + cl + 32; }
            d = fmaf(-2.f, a01, e2s[cl]);      if (d < bd1) { bd1 = d; bi1 = tb + cl; }
            d = fmaf(-2.f, a11, e2s[cl + 32]); if (d < bd1) { bd1 = d; bi1 = tb + cl + 32; }
        }
        // warp lexicographic argmin (dist, then index)
#pragma unroll
        for (int off = 16; off; off >>= 1) {
            float od = __shfl_down_sync(~0u, bd0, off);
            int   oi = __shfl_down_sync(~0u, bi0, off);
            if (od < bd0 || (od == bd0 && oi < bi0)) { bd0 = od; bi0 = oi; }
            od = __shfl_down_sync(~0u, bd1, off);
            oi = __shfl_down_sync(~0u, bi1, off);
            if (od < bd1 || (od == bd1 && oi < bi1)) { bd1 = od; bi1 = oi; }
        }
        if (cl == 0) { win[b0] = bi0; win[b1] = bi1; }
        __syncthreads();
        int w0 = win[b0], w1 = win[b1];
        float4 e0 = *(const float4*)&emb[((size_t)s * KCODES + w0) * DD + cl * 4];
        float4 e1 = *(const float4*)&emb[((size_t)s * KCODES + w1) * DD + cl * 4];
        float4 d0 = f4sub(e0, ca), d1 = f4sub(e1, cb);
        loss += dot4(d0, d0) + dot4(d1, d1);
        q0 = f4add(q0, e0); q1 = f4add(q1, e1);
    }
    *(float4*)&g_zq[(size_t)(B0 + b0) * DD + cl * 4] = q0;
    *(float4*)&g_zq[(size_t)(B0 + b1) * DD + cl * 4] = q1;

#pragma unroll
    for (int off = 16; off; off >>= 1) loss += __shfl_down_sync(~0u, loss, off);
    if (cl == 0) lred[bp] = loss;
    __syncthreads();
    if (t == 0) {
        float s = 0.f;
        for (int i = 0; i < 8; ++i) s += lred[i];
        g_lpart[blockIdx.x] = s;   // deterministic: no atomics
    }
}

// -------- kernel 3: betas[l][b][h] = mod_W[l,h,:]·zq[b] + mod_b[l,h] --------
// grid (B/64, LH/64); 64x64 output tile, K=128.
__global__ __launch_bounds__(256) void k_betas(
    const float* __restrict__ mW, const float* __restrict__ mb)
{
    extern __shared__ float sm[];
    float* Zs = sm;                 // [64][129]
    float* Ws = sm + 64 * 129;      // [64][129]
    const int t = threadIdx.x;
    const int i0 = blockIdx.x * 64, r0 = blockIdx.y * 64;
    for (int lin = t; lin < 8192; lin += 256) {
        int r = lin >> 7, k = lin & 127;
        Zs[r * 129 + k] = g_zq[(size_t)(i0 + r) * DD + k];
        Ws[r * 129 + k] = mW[(size_t)(r0 + r) * DD + k];
    }
    __syncthreads();
    const int ix = t & 15, wy = t >> 4;
    float acc[4][4] = {};
    for (int k = 0; k < 128; ++k) {
        float z[4], w[4];
#pragma unroll
        for (int m = 0; m < 4; ++m) {
            z[m] = Zs[(ix + 16 * m) * 129 + k];
            w[m] = Ws[(wy + 16 * m) * 129 + k];
        }
#pragma unroll
        for (int m = 0; m < 4; ++m)
#pragma unroll
            for (int n = 0; n < 4; ++n) acc[m][n] = fmaf(z[m], w[n], acc[m][n]);
    }
#pragma unroll
    for (int n = 0; n < 4; ++n) {
        float bias = mb[r0 + wy + 16 * n];
#pragma unroll
        for (int m = 0; m < 4; ++m)
            g_bet[(size_t)(i0 + ix + 16 * m) * LH + r0 + wy + 16 * n] = acc[m][n] + bias;
    }
}

// -------- kernel 4: fused modulated MLP, one image per block --------
// Xs[k][p] stride 68 (conflict-free LDS.128 reads & STS.128 epilogue writes).
// W panels [n][kk] stride 33, double-buffered with LDG->reg prefetch.
// 8x8 micro-tile per thread as f32x2 packed accumulators.
__global__ __launch_bounds__(256, 1) void k_mlp(
    const float* __restrict__ coords, const float* __restrict__ W0,
    const float* __restrict__ b0v, const float* __restrict__ Wh,
    const float* __restrict__ bh, const float* __restrict__ lW,
    const float* __restrict__ lb, float* __restrict__ out)
{
    extern __shared__ float sm[];
    float* Xs = sm;                  // 256*68 = 17408 floats
    float* Wp = sm + 17408;          // 2*8448 floats (also W0 / lastW staging)
    const int t = threadIdx.x, b = blockIdx.x;
    const int pg = t & 7, ng = t >> 3;
    const int p0 = pg * 8, n0 = ng * 8;
    const float* betb = g_bet + (size_t)b * LH;

    // positional encoding into Xs rows 0..41 (double trig: fast-math safe)
    if (t < 64) {
        float cx = coords[(size_t)(b * 64 + t) * 2];
        float cy = coords[(size_t)(b * 64 + t) * 2 + 1];
        Xs[t] = cx; Xs[68 + t] = cy;
        float fr = 3.14159274101257324f;   // float32(pi)
#pragma unroll
        for (int f = 0; f < 10; ++f) {
            float ax = cx * fr, ay = cy * fr;
            Xs[(2 + f) * 68 + t]  = (float)sin((double)ax);
            Xs[(12 + f) * 68 + t] = (float)sin((double)ay);
            Xs[(22 + f) * 68 + t] = (float)cos((double)ax);
            Xs[(32 + f) * 68 + t] = (float)cos((double)ay);
            fr *= 2.f;
        }
    }
    // stage W0 (256x42) as Wp[n*43+k]
    for (int lin = t; lin < 256 * 42; lin += 256) {
        int n = lin / 42, k = lin - n * 42;
        Wp[n * 43 + k] = W0[lin];
    }
    __syncthreads();

    ull acc[8][4];

    // ---- layer 0: K=42 ----
#pragma unroll
    for (int j = 0; j < 8; ++j)
#pragma unroll
        for (int q = 0; q < 4; ++q) acc[j][q] = pk2(0.f, 0.f);
    for (int k = 0; k < 42; ++k) {
        float4 xa0 = *(float4*)&Xs[k * 68 + p0];
        float4 xa1 = *(float4*)&Xs[k * 68 + p0 + 4];
        ull ax0 = pk2(xa0.x, xa0.y), ax1 = pk2(xa0.z, xa0.w);
        ull ax2 = pk2(xa1.x, xa1.y), ax3 = pk2(xa1.z, xa1.w);
#pragma unroll
        for (int j = 0; j < 8; ++j) {
            float w = Wp[(n0 + j) * 43 + k];
            ull ww = pk2(w, w);
            fma2(acc[j][0], ax0, ww); fma2(acc[j][1], ax1, ww);
            fma2(acc[j][2], ax2, ww); fma2(acc[j][3], ax3, ww);
        }
    }
    __syncthreads();   // all enc reads done before overwriting Xs
#pragma unroll
    for (int j = 0; j < 8; ++j) {
        float bb = b0v[n0 + j] + betb[n0 + j];
        float v[8];
#pragma unroll
        for (int q = 0; q < 4; ++q) {
            float x, y; upk2(acc[j][q], x, y);
            v[2 * q]     = fmaxf(x + bb, 0.f);
            v[2 * q + 1] = fmaxf(y + bb, 0.f);
        }
        *(float4*)&Xs[(n0 + j) * 68 + p0]     = make_float4(v[0], v[1], v[2], v[3]);
        *(float4*)&Xs[(n0 + j) * 68 + p0 + 4] = make_float4(v[4], v[5], v[6], v[7]);
    }
    __syncthreads();

    // ---- hidden layers 1..4: K=256, 8 panels of 32 ----
    for (int L = 1; L < LLAY; ++L) {
        const float* Wg = Wh + (size_t)(L - 1) * HH * HH;
        float4 pf[8];
#pragma unroll
        for (int i = 0; i < 8; ++i) {
            int lin = t + 256 * i, n = lin >> 3, c = lin & 7;
            pf[i] = *(const float4*)&Wg[n * 256 + c * 4];
        }
#pragma unroll
        for (int i = 0; i < 8; ++i) {
            int lin = t + 256 * i, n = lin >> 3, c = lin & 7;
            float* d = &Wp[n * 33 + c * 4];
            d[0] = pf[i].x; d[1] = pf[i].y; d[2] = pf[i].z; d[3] = pf[i].w;
        }
        __syncthreads();
#pragma unroll
        for (int j = 0; j < 8; ++j)
#pragma unroll
            for (int q = 0; q < 4; ++q) acc[j][q] = pk2(0.f, 0.f);

        for (int pnl = 0; pnl < 8; ++pnl) {
            const float* Wb = Wp + (pnl & 1) * 8448;
            if (pnl < 7) {
                int k0 = (pnl + 1) * 32;
#pragma unroll
                for (int i = 0; i < 8; ++i) {
                    int lin = t + 256 * i, n = lin >> 3, c = lin & 7;
                    pf[i] = *(const float4*)&Wg[n * 256 + k0 + c * 4];
                }
            }
            int kb = pnl * 32;
#pragma unroll 2
            for (int kk = 0; kk < 32; ++kk) {
                int k = kb + kk;
                float4 xa0 = *(float4*)&Xs[k * 68 + p0];
                float4 xa1 = *(float4*)&Xs[k * 68 + p0 + 4];
                ull ax0 = pk2(xa0.x, xa0.y), ax1 = pk2(xa0.z, xa0.w);
                ull ax2 = pk2(xa1.x, xa1.y), ax3 = pk2(xa1.z, xa1.w);
#pragma unroll
                for (int j = 0; j < 8; ++j) {
                    float w = Wb[(n0 + j) * 33 + kk];
                    ull ww = pk2(w, w);
                    fma2(acc[j][0], ax0, ww); fma2(acc[j][1], ax1, ww);
                    fma2(acc[j][2], ax2, ww); fma2(acc[j][3], ax3, ww);
                }
            }
            if (pnl < 7) {
                float* Wn = Wp + ((pnl + 1) & 1) * 8448;
#pragma unroll
                for (int i = 0; i < 8; ++i) {
                    int lin = t + 256 * i, n = lin >> 3, c = lin & 7;
                    float* d = &Wn[n * 33 + c * 4];
                    d[0] = pf[i].x; d[1] = pf[i].y; d[2] = pf[i].z; d[3] = pf[i].w;
                }
            }
            __syncthreads();
        }
        const float* bhp = bh + (size_t)(L - 1) * HH;
#pragma unroll
        for (int j = 0; j < 8; ++j) {
            float bb = bhp[n0 + j] + betb[L * HH + n0 + j];
            float v[8];
#pragma unroll
            for (int q = 0; q < 4; ++q) {
                float x, y; upk2(acc[j][q], x, y);
                v[2 * q]     = fmaxf(x + bb, 0.f);
                v[2 * q + 1] = fmaxf(y + bb, 0.f);
            }
            *(float4*)&Xs[(n0 + j) * 68 + p0]     = make_float4(v[0], v[1], v[2], v[3]);
            *(float4*)&Xs[(n0 + j) * 68 + p0 + 4] = make_float4(v[4], v[5], v[6], v[7]);
        }
        __syncthreads();
    }

    // ---- final layer: V=3 ----
    for (int lin = t; lin < 768; lin += 256) Wp[lin] = lW[lin];
    __syncthreads();
    if (t < 192) {
        int p = t / 3, v = t - p * 3;
        float s = 0.f;
        for (int h = 0; h < 256; ++h) s = fmaf(Xs[h * 68 + p], Wp[v * 256 + h], s);
        out[((size_t)b * 64 + p) * 3 + v] = s + lb[v];
    }
}

// -------- kernel 5: deterministic loss finalize --------
__global__ void k_loss(float* out, int has) {
    if (!has) return;
    float s = 0.f;
    for (int i = 0; i < 256; ++i) s += g_lpart[i];
    out[786432] = s * (0.25f / (4096.f * 128.f));
}

extern "C" void kernel_launch(void* const* d_in, const int* in_sizes, int n_in,
                              void* d_out, int out_size) {
    const float* coords = (const float*)d_in[0];
    const int*   li     = (const int*)d_in[1];
    const float* lat    = (const float*)d_in[2];
    const float* emb    = (const float*)d_in[3];
    const float* mW     = (const float*)d_in[4];
    const float* mb     = (const float*)d_in[5];
    const float* W0     = (const float*)d_in[6];
    const float* b0v    = (const float*)d_in[7];
    const float* Wh     = (const float*)d_in[8];
    const float* bh     = (const float*)d_in[9];
    const float* lW     = (const float*)d_in[10];
    const float* lb     = (const float*)d_in[11];
    float* out = (float*)d_out;

    cudaFuncSetAttribute(k_mlp,   cudaFuncAttributeMaxDynamicSharedMemorySize, 137216);
    cudaFuncSetAttribute(k_betas, cudaFuncAttributeMaxDynamicSharedMemorySize, 66048);

    k_e2<<<32, 256>>>(emb);
    k_vq<<<256, 256>>>(li, lat, emb);
    k_betas<<<dim3(64, 20), 256, 66048>>>(mW, mb);
    k_mlp<<<4096, 256, 137216>>>(coords, W0, b0v, Wh, bh, lW, lb, out);
    k_loss<<<1, 1>>>(out, out_size > 786432 ? 1 : 0);
}

// round 8
// speedup vs baseline: 1.9109x; 1.9109x over previous
#include <cuda_runtime.h>
#include <cuda_bf16.h>
#include <math.h>

#define BSZ 4096
#define DDIM 128
#define KCODES 2048
#define SSTG 4
#define LHTOT 1280

// -------- device scratch (static; no allocation) --------
__device__ float g_zq[BSZ * DDIM];
__device__ float g_bet[BSZ * LHTOT];
__device__ float g_e2[SSTG * KCODES];
__device__ float g_lpart[256];
__device__ __nv_bfloat16 g_W0h[256 * 64], g_W0l[256 * 64];
__device__ __nv_bfloat16 g_Whh[4 * 256 * 256], g_Whl[4 * 256 * 256];

typedef unsigned long long ull;

// -------- generic helpers --------
__device__ __forceinline__ float dot4(float4 a, float4 b) {
    return fmaf(a.x, b.x, fmaf(a.y, b.y, fmaf(a.z, b.z, a.w * b.w)));
}
__device__ __forceinline__ float4 f4add(float4 a, float4 b) {
    return make_float4(a.x + b.x, a.y + b.y, a.z + b.z, a.w + b.w);
}
__device__ __forceinline__ float4 f4sub(float4 a, float4 b) {
    return make_float4(a.x - b.x, a.y - b.y, a.z - b.z, a.w - b.w);
}
__device__ __forceinline__ unsigned smem_u32(const void* p) {
    unsigned a;
    asm("{ .reg .u64 t; cvta.to.shared.u64 t, %1; cvt.u32.u64 %0, t; }" : "=r"(a) : "l"(p));
    return a;
}
__device__ __forceinline__ void sts128(unsigned a, unsigned x, unsigned y, unsigned z, unsigned w) {
    asm volatile("st.shared.v4.b32 [%0], {%1,%2,%3,%4};" :: "r"(a), "r"(x), "r"(y), "r"(z), "r"(w));
}
__device__ __forceinline__ void sts32(unsigned a, unsigned v) {
    asm volatile("st.shared.u32 [%0], %1;" :: "r"(a), "r"(v));
}
__device__ __forceinline__ void sts16(unsigned a, unsigned short v) {
    asm volatile("st.shared.u16 [%0], %1;" :: "r"(a), "h"(v));
}
__device__ __forceinline__ unsigned lds32(unsigned a) {
    unsigned v; asm volatile("ld.shared.b32 %0, [%1];" : "=r"(v) : "r"(a)); return v;
}

// ldmatrix x4 (non-transposed), baseline PTX (sm_75+)
__device__ __forceinline__ void ldm4(unsigned* r, unsigned a) {
    asm volatile("ldmatrix.sync.aligned.m8n8.x4.shared.b16 {%0,%1,%2,%3}, [%4];"
        : "=r"(r[0]), "=r"(r[1]), "=r"(r[2]), "=r"(r[3]) : "r"(a));
}
// mma m16n8k16 bf16 -> f32 accum, baseline PTX (sm_80+)
__device__ __forceinline__ void mma_bf16(float* c, const unsigned* a, unsigned b0, unsigned b1) {
    asm volatile("mma.sync.aligned.m16n8k16.row.col.f32.bf16.bf16.f32 "
        "{%0,%1,%2,%3},{%4,%5,%6,%7},{%8,%9},{%0,%1,%2,%3};"
        : "+f"(c[0]), "+f"(c[1]), "+f"(c[2]), "+f"(c[3])
        : "r"(a[0]), "r"(a[1]), "r"(a[2]), "r"(a[3]), "r"(b0), "r"(b1));
}

// pack (lo, hi) floats -> bf16x2 (low half = lo)
__device__ __forceinline__ unsigned pbf2(float lo, float hi) {
    __nv_bfloat162 h = __floats2bfloat162_rn(lo, hi);
    return *(unsigned*)&h;
}

// accurate fp32 sincos (Cody-Waite; |a| <= 2^9*pi)
__device__ __forceinline__ void sc_f32(float a, float& s, float& c) {
    float n = rintf(a * 0.31830988618f);
    float r = fmaf(-n, 3.140625f, a);
    r = fmaf(-n, 9.67502593994140625e-4f, r);
    r = fmaf(-n, 1.50995788e-7f, r);
    float r2 = r * r;
    float sp = fmaf(r2, fmaf(r2, fmaf(r2, fmaf(r2, fmaf(r2, -2.5052108e-8f, 2.7557319e-6f),
               -1.9841270e-4f), 8.3333333e-3f), -1.6666667e-1f), 1.f);
    float cp = fmaf(r2, fmaf(r2, fmaf(r2, fmaf(r2, fmaf(r2, -2.7557319e-7f, 2.4801587e-5f),
               -1.3888889e-3f), 4.1666667e-2f), -0.5f), 1.f);
    s = r * sp; c = cp;
    if (((int)n) & 1) { s = -s; c = -c; }
}

// ======================================================================
// kernel 1: ||e||^2
// ======================================================================
__global__ void k_e2(const float* __restrict__ emb) {
    int c = blockIdx.x * 256 + threadIdx.x;
    const float4* row = (const float4*)(emb + (size_t)c * DDIM);
    float s = 0.f;
#pragma unroll 8
    for (int i = 0; i < 32; ++i) {
        float4 v = row[i];
        s += v.x * v.x + v.y * v.y + v.z * v.z + v.w * v.w;
    }
    g_e2[c] = s;
}

// ======================================================================
// kernel 2: residual VQ (unchanged; validated in R4)
// ======================================================================
__global__ __launch_bounds__(256) void k_vq(
    const int* __restrict__ li, const float* __restrict__ lat,
    const float* __restrict__ emb)
{
    __shared__ float4 zc4[16 * 32];
    __shared__ float4 em4[64 * 33];
    __shared__ float  e2s[64];
    __shared__ int    win[16];
    __shared__ float  lred[8];

    const int t = threadIdx.x, bp = t >> 5, cl = t & 31;
    const int b0 = 2 * bp, b1 = b0 + 1;
    const int B0 = blockIdx.x * 16;
    const int l0 = li[B0 + b0], l1 = li[B0 + b1];

    float4 r0 = make_float4(0, 0, 0, 0), r1 = r0, q0 = r0, q1 = r0;
    float loss = 0.f;

    for (int s = 0; s < SSTG; ++s) {
        float4 z0 = *(const float4*)&lat[((size_t)l0 * SSTG + s) * DDIM + cl * 4];
        float4 z1 = *(const float4*)&lat[((size_t)l1 * SSTG + s) * DDIM + cl * 4];
        r0 = f4add(r0, z0); r1 = f4add(r1, z1);
        float4 ca = f4sub(r0, q0), cb = f4sub(r1, q1);
        zc4[b0 * 32 + cl] = ca;
        zc4[b1 * 32 + cl] = cb;

        float bd0 = 3.4e38f, bd1 = 3.4e38f;
        int bi0 = 0, bi1 = 0;

        for (int tb = 0; tb < KCODES; tb += 64) {
            __syncthreads();
#pragma unroll
            for (int i = 0; i < 8; ++i) {
                int lin = t + 256 * i;
                int c = lin >> 5, k4 = lin & 31;
                em4[c * 33 + k4] =
                    *(const float4*)&emb[((size_t)s * KCODES + tb + c) * DDIM + k4 * 4];
            }
            if (t < 64) e2s[t] = g_e2[s * KCODES + tb + t];
            __syncthreads();

            float a00 = 0, a01 = 0, a10 = 0, a11 = 0;
#pragma unroll 4
            for (int k4 = 0; k4 < 32; ++k4) {
                float4 za = zc4[b0 * 32 + k4];
                float4 zb = zc4[b1 * 32 + k4];
                float4 e0 = em4[cl * 33 + k4];
                float4 e1 = em4[(cl + 32) * 33 + k4];
                a00 += dot4(e0, za); a01 += dot4(e0, zb);
                a10 += dot4(e1, za); a11 += dot4(e1, zb);
            }
            float d;
            d = fmaf(-2.f, a00, e2s[cl]);      if (d < bd0) { bd0 = d; bi0 = tb + cl; }
            d = fmaf(-2.f, a10, e2s[cl + 32]); if (d < bd0) { bd0 = d; bi0 = tb + cl + 32; }
            d = fmaf(-2.f, a01, e2s[cl]);      if (d < bd1) { bd1 = d; bi1 = tb + cl; }
            d = fmaf(-2.f, a11, e2s[cl + 32]); if (d < bd1) { bd1 = d; bi1 = tb + cl + 32; }
        }
#pragma unroll
        for (int off = 16; off; off >>= 1) {
            float od = __shfl_down_sync(~0u, bd0, off);
            int   oi = __shfl_down_sync(~0u, bi0, off);
            if (od < bd0 || (od == bd0 && oi < bi0)) { bd0 = od; bi0 = oi; }
            od = __shfl_down_sync(~0u, bd1, off);
            oi = __shfl_down_sync(~0u, bi1, off);
            if (od < bd1 || (od == bd1 && oi < bi1)) { bd1 = od; bi1 = oi; }
        }
        if (cl == 0) { win[b0] = bi0; win[b1] = bi1; }
        __syncthreads();
        int w0 = win[b0], w1 = win[b1];
        float4 e0 = *(const float4*)&emb[((size_t)s * KCODES + w0) * DDIM + cl * 4];
        float4 e1 = *(const float4*)&emb[((size_t)s * KCODES + w1) * DDIM + cl * 4];
        float4 d0 = f4sub(e0, ca), d1 = f4sub(e1, cb);
        loss += dot4(d0, d0) + dot4(d1, d1);
        q0 = f4add(q0, e0); q1 = f4add(q1, e1);
    }
    *(float4*)&g_zq[(size_t)(B0 + b0) * DDIM + cl * 4] = q0;
    *(float4*)&g_zq[(size_t)(B0 + b1) * DDIM + cl * 4] = q1;

#pragma unroll
    for (int off = 16; off; off >>= 1) loss += __shfl_down_sync(~0u, loss, off);
    if (cl == 0) lred[bp] = loss;
    __syncthreads();
    if (t == 0) {
        float s = 0.f;
        for (int i = 0; i < 8; ++i) s += lred[i];
        g_lpart[blockIdx.x] = s;
    }
}

// ======================================================================
// kernel 3: betas (unchanged; validated in R4)
// ======================================================================
__global__ __launch_bounds__(256) void k_betas(
    const float* __restrict__ mW, const float* __restrict__ mb)
{
    extern __shared__ float sm[];
    float* Zs = sm;
    float* Ws = sm + 64 * 129;
    const int t = threadIdx.x;
    const int i0 = blockIdx.x * 64, r0 = blockIdx.y * 64;
    for (int lin = t; lin < 8192; lin += 256) {
        int r = lin >> 7, k = lin & 127;
        Zs[r * 129 + k] = g_zq[(size_t)(i0 + r) * DDIM + k];
        Ws[r * 129 + k] = mW[(size_t)(r0 + r) * DDIM + k];
    }
    __syncthreads();
    const int ix = t & 15, wy = t >> 4;
    float acc[4][4] = {};
    for (int k = 0; k < 128; ++k) {
        float z[4], w[4];
#pragma unroll
        for (int m = 0; m < 4; ++m) {
            z[m] = Zs[(ix + 16 * m) * 129 + k];
            w[m] = Ws[(wy + 16 * m) * 129 + k];
        }
#pragma unroll
        for (int m = 0; m < 4; ++m)
#pragma unroll
            for (int n = 0; n < 4; ++n) acc[m][n] = fmaf(z[m], w[n], acc[m][n]);
    }
#pragma unroll
    for (int n = 0; n < 4; ++n) {
        float bias = mb[r0 + wy + 16 * n];
#pragma unroll
        for (int m = 0; m < 4; ++m)
            g_bet[(size_t)(i0 + ix + 16 * m) * LHTOT + r0 + wy + 16 * n] = acc[m][n] + bias;
    }
}

// ======================================================================
// kernel 4: bf16 hi/lo weight split (W0 padded 42->64)
// ======================================================================
__global__ void k_wprep(const float* __restrict__ W0, const float* __restrict__ Wh) {
    int i = blockIdx.x * 256 + threadIdx.x;
    if (i < 256 * 64) {
        int n = i >> 6, k = i & 63;
        float w = (k < 42) ? W0[n * 42 + k] : 0.f;
        __nv_bfloat16 h = __float2bfloat16(w);
        g_W0h[i] = h;
        g_W0l[i] = __float2bfloat16(w - __bfloat162float(h));
    }
    if (i < 4 * 256 * 256) {
        float w = Wh[i];
        __nv_bfloat16 h = __float2bfloat16(w);
        g_Whh[i] = h;
        g_Whl[i] = __float2bfloat16(w - __bfloat162float(h));
    }
}

// ======================================================================
// kernel 5: mma.sync (HMMA) fused MLP — 2 images/CTA, M=128, N=256
// X planes: bf16 [m=128][k stride 264] hi+lo (67584 B each)
// W panel : bf16 [n=256][k=64 stride 72] hi+lo (36864 B each)
// warps: wm = wid&1 (m-half), wn = wid>>1 (n-quarter), warp tile 64x64
// ======================================================================
__global__ __launch_bounds__(256, 1) void k_mlp_mma(
    const float* __restrict__ coords, const float* __restrict__ b0v,
    const float* __restrict__ bhv, const float* __restrict__ lW,
    const float* __restrict__ lb, float* __restrict__ out)
{
    extern __shared__ char dyn[];
    __shared__ float bbs[512];
    __shared__ float lWs[768];

    const unsigned SB = smem_u32(dyn);
    const unsigned XHI = SB, XLO = SB + 67584u;
    const unsigned WHI = SB + 135168u, WLO = SB + 172032u;

    const int t = threadIdx.x, wid = t >> 5, l = t & 31;
    const int wm = wid & 1, wn = wid >> 1;
    const int blk = blockIdx.x;

    // ---- positional encoding -> X planes rows 0..127, cols 0..63 ----
    if (t < 128) {
        const float* cp = coords + ((size_t)(blk * 2) * 64 + t) * 2;
        float cx = cp[0], cy = cp[1];
        unsigned rowo = (unsigned)t * 528u;
        auto wrf = [&](int k, float v) {
            __nv_bfloat16 h = __float2bfloat16(v);
            float hf = __bfloat162float(h);
            __nv_bfloat16 lo = __float2bfloat16(v - hf);
            sts16(XHI + rowo + 2u * k, *(unsigned short*)&h);
            sts16(XLO + rowo + 2u * k, *(unsigned short*)&lo);
        };
        wrf(0, cx); wrf(1, cy);
        float fr = 3.14159274101257324f;
#pragma unroll
        for (int f = 0; f < 10; ++f) {
            float sx, cxv, sy, cyv;
            sc_f32(cx * fr, sx, cxv);
            sc_f32(cy * fr, sy, cyv);
            wrf(2 + f, sx); wrf(12 + f, sy);
            wrf(22 + f, cxv); wrf(32 + f, cyv);
            fr *= 2.f;
        }
#pragma unroll
        for (int k = 42; k < 64; ++k) wrf(k, 0.f);
    }

    float acc[4][8][4];

    // per-lane fragment address components
    const unsigned aoffb = (unsigned)(wm * 64 + (l & 15)) * 528u + (unsigned)((l >> 4) << 3) * 2u;
    const unsigned boffb = ((unsigned)(wn * 64) + (unsigned)((l >> 4) << 3) + (unsigned)(l & 7)) * 144u
                         + (unsigned)(((l >> 3) & 1) << 3) * 2u;

#pragma unroll 1
    for (int L = 0; L < 5; ++L) {
        const int npanels = (L == 0) ? 1 : 4;
        const __nv_bfloat16* WhG = (L == 0) ? g_W0h : (g_Whh + (size_t)(L - 1) * 65536);
        const __nv_bfloat16* WlG = (L == 0) ? g_W0l : (g_Whl + (size_t)(L - 1) * 65536);
        const int rstride = (L == 0) ? 64 : 256;

#pragma unroll
        for (int mt = 0; mt < 4; ++mt)
#pragma unroll
            for (int nc = 0; nc < 8; ++nc)
#pragma unroll
                for (int q = 0; q < 4; ++q) acc[mt][nc][q] = 0.f;

#pragma unroll 1
        for (int p = 0; p < npanels; ++p) {
            __syncthreads();   // prior panel fully consumed
            {   // load W panel: thread t = row n
                const __nv_bfloat16* gh = WhG + (size_t)t * rstride + p * 64;
                const __nv_bfloat16* gl = WlG + (size_t)t * rstride + p * 64;
                unsigned sh = WHI + (unsigned)t * 144u;
                unsigned sl = WLO + (unsigned)t * 144u;
#pragma unroll
                for (int sg = 0; sg < 8; ++sg) {
                    uint4 v = *(const uint4*)(gh + sg * 8);
                    sts128(sh + sg * 16u, v.x, v.y, v.z, v.w);
                }
#pragma unroll
                for (int sg = 0; sg < 8; ++sg) {
                    uint4 v = *(const uint4*)(gl + sg * 8);
                    sts128(sl + sg * 16u, v.x, v.y, v.z, v.w);
                }
            }
            __syncthreads();

#pragma unroll 1
            for (int ks = 0; ks < 4; ++ks) {
                unsigned kg = (unsigned)(p * 64 + ks * 16) * 2u;   // X col byte offset
                unsigned kl = (unsigned)(ks * 16) * 2u;            // W col byte offset
                unsigned ahi[4][4], alo[4][4];
#pragma unroll
                for (int mt = 0; mt < 4; ++mt) {
                    ldm4(ahi[mt], XHI + aoffb + kg + (unsigned)mt * (16u * 528u));
                    ldm4(alo[mt], XLO + aoffb + kg + (unsigned)mt * (16u * 528u));
                }
#pragma unroll
                for (int bg = 0; bg < 4; ++bg) {
                    unsigned bo = boffb + (unsigned)bg * (16u * 144u) + kl;
                    unsigned bh[4], bl[4];
                    ldm4(bh, WHI + bo);
                    ldm4(bl, WLO + bo);
#pragma unroll
                    for (int mt = 0; mt < 4; ++mt) {
                        mma_bf16(acc[mt][2 * bg],     ahi[mt], bh[0], bh[1]);
                        mma_bf16(acc[mt][2 * bg + 1], ahi[mt], bh[2], bh[3]);
                        mma_bf16(acc[mt][2 * bg],     ahi[mt], bl[0], bl[1]);
                        mma_bf16(acc[mt][2 * bg + 1], ahi[mt], bl[2], bl[3]);
                        mma_bf16(acc[mt][2 * bg],     alo[mt], bh[0], bh[1]);
                        mma_bf16(acc[mt][2 * bg + 1], alo[mt], bh[2], bh[3]);
                    }
                }
            }
        }
        __syncthreads();   // all warps done reading X for this layer

        for (int i = t; i < 512; i += 256) {
            int img = i >> 8, n = i & 255;
            float bias = (L == 0) ? b0v[n] : bhv[(L - 1) * 256 + n];
            bbs[i] = bias + g_bet[(size_t)(blk * 2 + img) * LHTOT + L * 256 + n];
        }
        __syncthreads();

        // ---- epilogue: bias+beta+relu, bf16 hi/lo re-split, store to X ----
        {
            const float* bb = bbs + wm * 256;
#pragma unroll
            for (int mt = 0; mt < 4; ++mt) {
                unsigned ro0 = (unsigned)(wm * 64 + mt * 16 + (l >> 2)) * 528u;
                unsigned ro1 = ro0 + 8u * 528u;
#pragma unroll
                for (int nc = 0; nc < 8; ++nc) {
                    int cb = wn * 64 + nc * 8 + (l & 3) * 2;
                    float b0f = bb[cb], b1f = bb[cb + 1];
                    float x0 = fmaxf(acc[mt][nc][0] + b0f, 0.f);
                    float x1 = fmaxf(acc[mt][nc][1] + b1f, 0.f);
                    float y0 = fmaxf(acc[mt][nc][2] + b0f, 0.f);
                    float y1 = fmaxf(acc[mt][nc][3] + b1f, 0.f);
                    unsigned hp0 = pbf2(x0, x1);
                    unsigned hp1 = pbf2(y0, y1);
                    unsigned lp0 = pbf2(x0 - __uint_as_float(hp0 << 16),
                                        x1 - __uint_as_float(hp0 & 0xFFFF0000u));
                    unsigned lp1 = pbf2(y0 - __uint_as_float(hp1 << 16),
                                        y1 - __uint_as_float(hp1 & 0xFFFF0000u));
                    unsigned co = (unsigned)cb * 2u;
                    sts32(XHI + ro0 + co, hp0);
                    sts32(XLO + ro0 + co, lp0);
                    sts32(XHI + ro1 + co, hp1);
                    sts32(XLO + ro1 + co, lp1);
                }
            }
        }
        __syncthreads();
    }

    // ---- final linear layer: V=3, fp32 from hi+lo planes ----
    for (int i = t; i < 768; i += 256) lWs[i] = lW[i];
    __syncthreads();
    if (t < 128) {
        float a0 = 0.f, a1 = 0.f, a2 = 0.f;
        unsigned xh = XHI + (unsigned)t * 528u, xl = XLO + (unsigned)t * 528u;
#pragma unroll 8
        for (int k2 = 0; k2 < 128; ++k2) {
            unsigned hv = lds32(xh + k2 * 4u), lv = lds32(xl + k2 * 4u);
            float x0 = __uint_as_float(hv << 16) + __uint_as_float(lv << 16);
            float x1 = __uint_as_float(hv & 0xFFFF0000u) + __uint_as_float(lv & 0xFFFF0000u);
            int k = 2 * k2;
            a0 = fmaf(x0, lWs[k], fmaf(x1, lWs[k + 1], a0));
            a1 = fmaf(x0, lWs[256 + k], fmaf(x1, lWs[256 + k + 1], a1));
            a2 = fmaf(x0, lWs[512 + k], fmaf(x1, lWs[512 + k + 1], a2));
        }
        size_t ob = ((size_t)blk * 128 + t) * 3;
        out[ob]     = a0 + lb[0];
        out[ob + 1] = a1 + lb[1];
        out[ob + 2] = a2 + lb[2];
    }
}

// ======================================================================
// kernel 6: deterministic loss finalize
// ======================================================================
__global__ void k_loss(float* out, int has) {
    if (!has) return;
    float s = 0.f;
    for (int i = 0; i < 256; ++i) s += g_lpart[i];
    out[786432] = s * (0.25f / (4096.f * 128.f));
}

extern "C" void kernel_launch(void* const* d_in, const int* in_sizes, int n_in,
                              void* d_out, int out_size) {
    const float* coords = (const float*)d_in[0];
    const int*   li     = (const int*)d_in[1];
    const float* lat    = (const float*)d_in[2];
    const float* emb    = (const float*)d_in[3];
    const float* mW     = (const float*)d_in[4];
    const float* mb     = (const float*)d_in[5];
    const float* W0     = (const float*)d_in[6];
    const float* b0v    = (const float*)d_in[7];
    const float* Wh     = (const float*)d_in[8];
    const float* bh     = (const float*)d_in[9];
    const float* lW     = (const float*)d_in[10];
    const float* lb     = (const float*)d_in[11];
    float* out = (float*)d_out;

    const int MLP_SMEM = 208896;   // X hi/lo (2*67584) + W hi/lo (2*36864)
    cudaFuncSetAttribute(k_mlp_mma, cudaFuncAttributeMaxDynamicSharedMemorySize, MLP_SMEM);
    cudaFuncSetAttribute(k_betas,   cudaFuncAttributeMaxDynamicSharedMemorySize, 66048);

    k_e2<<<32, 256>>>(emb);
    k_vq<<<256, 256>>>(li, lat, emb);
    k_betas<<<dim3(64, 20), 256, 66048>>>(mW, mb);
    k_wprep<<<1024, 256>>>(W0, Wh);
    k_mlp_mma<<<2048, 256, MLP_SMEM>>>(coords, b0v, bh, lW, lb, out);
    k_loss<<<1, 1>>>(out, out_size > 786432 ? 1 : 0);
}

// round 9
// speedup vs baseline: 3.6904x; 1.9313x over previous
#include <cuda_runtime.h>
#include <cuda_bf16.h>
#include <cuda_fp16.h>
#include <math.h>

#define BSZ 4096
#define DDIM 128
#define KCODES 2048
#define SSTG 4
#define LHTOT 1280

// -------- device scratch (static; no allocation) --------
__device__ float g_zq[BSZ * DDIM];
__device__ float g_bet[BSZ * LHTOT];
__device__ float g_e2[SSTG * KCODES];
__device__ float g_lpart[256];
__device__ __half g_W0f[256 * 64];
__device__ __half g_Whf[4 * 256 * 256];

typedef unsigned long long ull;

// -------- generic helpers --------
__device__ __forceinline__ float dot4(float4 a, float4 b) {
    return fmaf(a.x, b.x, fmaf(a.y, b.y, fmaf(a.z, b.z, a.w * b.w)));
}
__device__ __forceinline__ float4 f4add(float4 a, float4 b) {
    return make_float4(a.x + b.x, a.y + b.y, a.z + b.z, a.w + b.w);
}
__device__ __forceinline__ float4 f4sub(float4 a, float4 b) {
    return make_float4(a.x - b.x, a.y - b.y, a.z - b.z, a.w - b.w);
}
__device__ __forceinline__ unsigned smem_u32(const void* p) {
    unsigned a;
    asm("{ .reg .u64 t; cvta.to.shared.u64 t, %1; cvt.u32.u64 %0, t; }" : "=r"(a) : "l"(p));
    return a;
}
__device__ __forceinline__ void sts32(unsigned a, unsigned v) {
    asm volatile("st.shared.u32 [%0], %1;" :: "r"(a), "r"(v));
}
__device__ __forceinline__ void sts16(unsigned a, unsigned short v) {
    asm volatile("st.shared.u16 [%0], %1;" :: "r"(a), "h"(v));
}
__device__ __forceinline__ unsigned lds32(unsigned a) {
    unsigned v; asm volatile("ld.shared.b32 %0, [%1];" : "=r"(v) : "r"(a)); return v;
}
__device__ __forceinline__ void ldm4(unsigned* r, unsigned a) {
    asm volatile("ldmatrix.sync.aligned.m8n8.x4.shared.b16 {%0,%1,%2,%3}, [%4];"
        : "=r"(r[0]), "=r"(r[1]), "=r"(r[2]), "=r"(r[3]) : "r"(a));
}
// fp16 mma m16n8k16 -> f32 accum (baseline sm_80)
__device__ __forceinline__ void mma_f16h(float* c, const unsigned* a, unsigned b0, unsigned b1) {
    asm volatile("mma.sync.aligned.m16n8k16.row.col.f32.f16.f16.f32 "
        "{%0,%1,%2,%3},{%4,%5,%6,%7},{%8,%9},{%0,%1,%2,%3};"
        : "+f"(c[0]), "+f"(c[1]), "+f"(c[2]), "+f"(c[3])
        : "r"(a[0]), "r"(a[1]), "r"(a[2]), "r"(a[3]), "r"(b0), "r"(b1));
}
__device__ __forceinline__ void cpa16(unsigned dst, const void* src) {
    asm volatile("cp.async.cg.shared.global [%0], [%1], 16;" :: "r"(dst), "l"(src));
}
#define CPA_COMMIT() asm volatile("cp.async.commit_group;" ::: "memory")
#define CPA_WAIT1()  asm volatile("cp.async.wait_group 1;" ::: "memory")
#define CPA_WAIT0()  asm volatile("cp.async.wait_group 0;" ::: "memory")

// accurate fp32 sincos (Cody-Waite; |a| <= 2^9*pi)
__device__ __forceinline__ void sc_f32(float a, float& s, float& c) {
    float n = rintf(a * 0.31830988618f);
    float r = fmaf(-n, 3.140625f, a);
    r = fmaf(-n, 9.67502593994140625e-4f, r);
    r = fmaf(-n, 1.50995788e-7f, r);
    float r2 = r * r;
    float sp = fmaf(r2, fmaf(r2, fmaf(r2, fmaf(r2, fmaf(r2, -2.5052108e-8f, 2.7557319e-6f),
               -1.9841270e-4f), 8.3333333e-3f), -1.6666667e-1f), 1.f);
    float cp = fmaf(r2, fmaf(r2, fmaf(r2, fmaf(r2, fmaf(r2, -2.7557319e-7f, 2.4801587e-5f),
               -1.3888889e-3f), 4.1666667e-2f), -0.5f), 1.f);
    s = r * sp; c = cp;
    if (((int)n) & 1) { s = -s; c = -c; }
}

// ======================================================================
// kernel 1: ||e||^2
// ======================================================================
__global__ void k_e2(const float* __restrict__ emb) {
    int c = blockIdx.x * 256 + threadIdx.x;
    const float4* row = (const float4*)(emb + (size_t)c * DDIM);
    float s = 0.f;
#pragma unroll 8
    for (int i = 0; i < 32; ++i) {
        float4 v = row[i];
        s += v.x * v.x + v.y * v.y + v.z * v.z + v.w * v.w;
    }
    g_e2[c] = s;
}

// ======================================================================
// kernel 2: residual VQ (validated)
// ======================================================================
__global__ __launch_bounds__(256) void k_vq(
    const int* __restrict__ li, const float* __restrict__ lat,
    const float* __restrict__ emb)
{
    __shared__ float4 zc4[16 * 32];
    __shared__ float4 em4[64 * 33];
    __shared__ float  e2s[64];
    __shared__ int    win[16];
    __shared__ float  lred[8];

    const int t = threadIdx.x, bp = t >> 5, cl = t & 31;
    const int b0 = 2 * bp, b1 = b0 + 1;
    const int B0 = blockIdx.x * 16;
    const int l0 = li[B0 + b0], l1 = li[B0 + b1];

    float4 r0 = make_float4(0, 0, 0, 0), r1 = r0, q0 = r0, q1 = r0;
    float loss = 0.f;

    for (int s = 0; s < SSTG; ++s) {
        float4 z0 = *(const float4*)&lat[((size_t)l0 * SSTG + s) * DDIM + cl * 4];
        float4 z1 = *(const float4*)&lat[((size_t)l1 * SSTG + s) * DDIM + cl * 4];
        r0 = f4add(r0, z0); r1 = f4add(r1, z1);
        float4 ca = f4sub(r0, q0), cb = f4sub(r1, q1);
        zc4[b0 * 32 + cl] = ca;
        zc4[b1 * 32 + cl] = cb;

        float bd0 = 3.4e38f, bd1 = 3.4e38f;
        int bi0 = 0, bi1 = 0;

        for (int tb = 0; tb < KCODES; tb += 64) {
            __syncthreads();
#pragma unroll
            for (int i = 0; i < 8; ++i) {
                int lin = t + 256 * i;
                int c = lin >> 5, k4 = lin & 31;
                em4[c * 33 + k4] =
                    *(const float4*)&emb[((size_t)s * KCODES + tb + c) * DDIM + k4 * 4];
            }
            if (t < 64) e2s[t] = g_e2[s * KCODES + tb + t];
            __syncthreads();

            float a00 = 0, a01 = 0, a10 = 0, a11 = 0;
#pragma unroll 4
            for (int k4 = 0; k4 < 32; ++k4) {
                float4 za = zc4[b0 * 32 + k4];
                float4 zb = zc4[b1 * 32 + k4];
                float4 e0 = em4[cl * 33 + k4];
                float4 e1 = em4[(cl + 32) * 33 + k4];
                a00 += dot4(e0, za); a01 += dot4(e0, zb);
                a10 += dot4(e1, za); a11 += dot4(e1, zb);
            }
            float d;
            d = fmaf(-2.f, a00, e2s[cl]);      if (d < bd0) { bd0 = d; bi0 = tb + cl; }
            d = fmaf(-2.f, a10, e2s[cl + 32]); if (d < bd0) { bd0 = d; bi0 = tb + cl + 32; }
            d = fmaf(-2.f, a01, e2s[cl]);      if (d < bd1) { bd1 = d; bi1 = tb + cl; }
            d = fmaf(-2.f, a11, e2s[cl + 32]); if (d < bd1) { bd1 = d; bi1 = tb + cl + 32; }
        }
#pragma unroll
        for (int off = 16; off; off >>= 1) {
            float od = __shfl_down_sync(~0u, bd0, off);
            int   oi = __shfl_down_sync(~0u, bi0, off);
            if (od < bd0 || (od == bd0 && oi < bi0)) { bd0 = od; bi0 = oi; }
            od = __shfl_down_sync(~0u, bd1, off);
            oi = __shfl_down_sync(~0u, bi1, off);
            if (od < bd1 || (od == bd1 && oi < bi1)) { bd1 = od; bi1 = oi; }
        }
        if (cl == 0) { win[b0] = bi0; win[b1] = bi1; }
        __syncthreads();
        int w0 = win[b0], w1 = win[b1];
        float4 e0 = *(const float4*)&emb[((size_t)s * KCODES + w0) * DDIM + cl * 4];
        float4 e1 = *(const float4*)&emb[((size_t)s * KCODES + w1) * DDIM + cl * 4];
        float4 d0 = f4sub(e0, ca), d1 = f4sub(e1, cb);
        loss += dot4(d0, d0) + dot4(d1, d1);
        q0 = f4add(q0, e0); q1 = f4add(q1, e1);
    }
    *(float4*)&g_zq[(size_t)(B0 + b0) * DDIM + cl * 4] = q0;
    *(float4*)&g_zq[(size_t)(B0 + b1) * DDIM + cl * 4] = q1;

#pragma unroll
    for (int off = 16; off; off >>= 1) loss += __shfl_down_sync(~0u, loss, off);
    if (cl == 0) lred[bp] = loss;
    __syncthreads();
    if (t == 0) {
        float s = 0.f;
        for (int i = 0; i < 8; ++i) s += lred[i];
        g_lpart[blockIdx.x] = s;
    }
}

// ======================================================================
// kernel 3: betas (validated)
// ======================================================================
__global__ __launch_bounds__(256) void k_betas(
    const float* __restrict__ mW, const float* __restrict__ mb)
{
    extern __shared__ float sm[];
    float* Zs = sm;
    float* Ws = sm + 64 * 129;
    const int t = threadIdx.x;
    const int i0 = blockIdx.x * 64, r0 = blockIdx.y * 64;
    for (int lin = t; lin < 8192; lin += 256) {
        int r = lin >> 7, k = lin & 127;
        Zs[r * 129 + k] = g_zq[(size_t)(i0 + r) * DDIM + k];
        Ws[r * 129 + k] = mW[(size_t)(r0 + r) * DDIM + k];
    }
    __syncthreads();
    const int ix = t & 15, wy = t >> 4;
    float acc[4][4] = {};
    for (int k = 0; k < 128; ++k) {
        float z[4], w[4];
#pragma unroll
        for (int m = 0; m < 4; ++m) {
            z[m] = Zs[(ix + 16 * m) * 129 + k];
            w[m] = Ws[(wy + 16 * m) * 129 + k];
        }
#pragma unroll
        for (int m = 0; m < 4; ++m)
#pragma unroll
            for (int n = 0; n < 4; ++n) acc[m][n] = fmaf(z[m], w[n], acc[m][n]);
    }
#pragma unroll
    for (int n = 0; n < 4; ++n) {
        float bias = mb[r0 + wy + 16 * n];
#pragma unroll
        for (int m = 0; m < 4; ++m)
            g_bet[(size_t)(i0 + ix + 16 * m) * LHTOT + r0 + wy + 16 * n] = acc[m][n] + bias;
    }
}

// ======================================================================
// kernel 4: fp16 weight conversion (W0 padded 42->64)
// ======================================================================
__global__ void k_wprep(const float* __restrict__ W0, const float* __restrict__ Wh) {
    int i = blockIdx.x * 256 + threadIdx.x;   // grid covers 262144
    if (i < 256 * 64) {
        int n = i >> 6, k = i & 63;
        float w = (k < 42) ? W0[n * 42 + k] : 0.f;
        g_W0f[i] = __float2half_rn(w);
    }
    g_Whf[i] = __float2half_rn(Wh[i]);
}

// ======================================================================
// kernel 5: fp16 HMMA fused MLP, cp.async double-buffered K=32 panels
//   2 images/CTA (M=128), N=256. X plane: fp16 [128][264] (stride 528 B).
//   W buffers: 2 x fp16 [256][40] (stride 80 B = 20 banks -> ldmatrix OK).
//   34 flat panels: layer0 = 2 (K 0..63), layers1..4 = 8 each.
// ======================================================================
__global__ __launch_bounds__(256, 1) void k_mlp16(
    const float* __restrict__ coords, const float* __restrict__ b0v,
    const float* __restrict__ bhv, const float* __restrict__ lW,
    const float* __restrict__ lb, float* __restrict__ out)
{
    extern __shared__ char dyn[];
    __shared__ float bbs[512];
    __shared__ float lWs[768];

    const unsigned XB = smem_u32(dyn);
    const unsigned WB = XB + 67584u;

    const int t = threadIdx.x, wid = t >> 5, l = t & 31;
    const int wm = wid & 1, wn = wid >> 1;
    const int blk = blockIdx.x;

    const unsigned aoffb = (unsigned)(wm * 64 + (l & 15)) * 528u + (unsigned)((l >> 4) << 3) * 2u;
    const unsigned boffb = (unsigned)(wn * 64 + ((l >> 4) << 3) + (l & 7)) * 80u
                         + (unsigned)(((l >> 3) & 1) << 3) * 2u;

    auto issue = [&](int g) {
        const __half* Wg; int rstride, k0;
        if (g < 2) { Wg = g_W0f; rstride = 64; k0 = g * 32; }
        else {
            int Lw = (g - 2) >> 3;
            Wg = g_Whf + (size_t)Lw * 65536; rstride = 256; k0 = ((g - 2) & 7) * 32;
        }
        const __half* src = Wg + (size_t)t * rstride + k0;
        unsigned dst = WB + (unsigned)(g & 1) * 20480u + (unsigned)t * 80u;
#pragma unroll
        for (int c = 0; c < 4; ++c) cpa16(dst + (unsigned)c * 16u, src + c * 8);
        CPA_COMMIT();
    };

    issue(0);

    // ---- positional encoding -> X rows (fp16), cols 42..63 zero ----
    if (t < 128) {
        const float* cp = coords + ((size_t)(blk * 2) * 64 + t) * 2;
        float cx = cp[0], cy = cp[1];
        unsigned rowo = XB + (unsigned)t * 528u;
        auto wrf = [&](int k, float v) {
            __half h = __float2half_rn(v);
            sts16(rowo + 2u * (unsigned)k, *(unsigned short*)&h);
        };
        wrf(0, cx); wrf(1, cy);
        float fr = 3.14159274101257324f;
#pragma unroll
        for (int f = 0; f < 10; ++f) {
            float sx, cxv, sy, cyv;
            sc_f32(cx * fr, sx, cxv);
            sc_f32(cy * fr, sy, cyv);
            wrf(2 + f, sx); wrf(12 + f, sy);
            wrf(22 + f, cxv); wrf(32 + f, cyv);
            fr *= 2.f;
        }
#pragma unroll
        for (int k = 42; k < 64; ++k) wrf(k, 0.f);
    }
    for (int i = t; i < 768; i += 256) lWs[i] = lW[i];
    __syncthreads();

    float acc[4][8][4];
#pragma unroll
    for (int mt = 0; mt < 4; ++mt)
#pragma unroll
        for (int nc = 0; nc < 8; ++nc)
#pragma unroll
            for (int q = 0; q < 4; ++q) acc[mt][nc][q] = 0.f;

    int L = 0;
#pragma unroll 1
    for (int g = 0; g < 34; ++g) {
        if (g + 1 < 34) { issue(g + 1); CPA_WAIT1(); } else { CPA_WAIT0(); }
        __syncthreads();

        const unsigned wb = WB + (unsigned)(g & 1) * 20480u;
        const int kb = (g < 2) ? g * 32 : ((g - 2) & 7) * 32;
#pragma unroll
        for (int ks = 0; ks < 2; ++ks) {
            unsigned xc = (unsigned)(kb + ks * 16) * 2u;
            unsigned a[4][4];
#pragma unroll
            for (int mt = 0; mt < 4; ++mt)
                ldm4(a[mt], XB + aoffb + xc + (unsigned)mt * (16u * 528u));
#pragma unroll
            for (int bg = 0; bg < 4; ++bg) {
                unsigned bf[4];
                ldm4(bf, wb + boffb + (unsigned)bg * (16u * 80u) + (unsigned)(ks * 32));
#pragma unroll
                for (int mt = 0; mt < 4; ++mt) {
                    mma_f16h(acc[mt][2 * bg],     a[mt], bf[0], bf[1]);
                    mma_f16h(acc[mt][2 * bg + 1], a[mt], bf[2], bf[3]);
                }
            }
        }

        const bool layerEnd = (g == 1) || (g >= 2 && ((g - 2) & 7) == 7);
        if (layerEnd) {
            __syncthreads();   // all warps done reading X & this W buf
            for (int i = t; i < 512; i += 256) {
                int img = i >> 8, n = i & 255;
                float bias = (L == 0) ? b0v[n] : bhv[(L - 1) * 256 + n];
                bbs[i] = bias + g_bet[(size_t)(blk * 2 + img) * LHTOT + L * 256 + n];
            }
            __syncthreads();
            const float* bb = bbs + wm * 256;
#pragma unroll
            for (int mt = 0; mt < 4; ++mt) {
                unsigned ro0 = XB + (unsigned)(wm * 64 + mt * 16 + (l >> 2)) * 528u;
                unsigned ro1 = ro0 + 8u * 528u;
#pragma unroll
                for (int nc = 0; nc < 8; ++nc) {
                    int cb = wn * 64 + nc * 8 + (l & 3) * 2;
                    float b0f = bb[cb], b1f = bb[cb + 1];
                    float x0 = fmaxf(acc[mt][nc][0] + b0f, 0.f);
                    float x1 = fmaxf(acc[mt][nc][1] + b1f, 0.f);
                    float y0 = fmaxf(acc[mt][nc][2] + b0f, 0.f);
                    float y1 = fmaxf(acc[mt][nc][3] + b1f, 0.f);
                    __half2 h0 = __floats2half2_rn(x0, x1);
                    __half2 h1 = __floats2half2_rn(y0, y1);
                    sts32(ro0 + (unsigned)cb * 2u, *(unsigned*)&h0);
                    sts32(ro1 + (unsigned)cb * 2u, *(unsigned*)&h1);
                    acc[mt][nc][0] = 0.f; acc[mt][nc][1] = 0.f;
                    acc[mt][nc][2] = 0.f; acc[mt][nc][3] = 0.f;
                }
            }
            ++L;
            __syncthreads();
        } else {
            __syncthreads();   // protect W buf reuse at iter g+1
        }
    }

    // ---- final linear layer: V=3, fp32 from fp16 plane ----
    if (t < 128) {
        float a0 = 0.f, a1 = 0.f, a2 = 0.f;
        unsigned xr = XB + (unsigned)t * 528u;
#pragma unroll 8
        for (int k2 = 0; k2 < 128; ++k2) {
            unsigned hv = lds32(xr + k2 * 4u);
            __half2 h = *(__half2*)&hv;
            float x0 = __half2float(h.x), x1 = __half2float(h.y);
            int k = 2 * k2;
            a0 = fmaf(x0, lWs[k], fmaf(x1, lWs[k + 1], a0));
            a1 = fmaf(x0, lWs[256 + k], fmaf(x1, lWs[256 + k + 1], a1));
            a2 = fmaf(x0, lWs[512 + k], fmaf(x1, lWs[512 + k + 1], a2));
        }
        size_t ob = ((size_t)blk * 128 + t) * 3;
        out[ob]     = a0 + lb[0];
        out[ob + 1] = a1 + lb[1];
        out[ob + 2] = a2 + lb[2];
    }
}

// ======================================================================
// kernel 6: deterministic loss finalize
// ======================================================================
__global__ void k_loss(float* out, int has) {
    if (!has) return;
    float s = 0.f;
    for (int i = 0; i < 256; ++i) s += g_lpart[i];
    out[786432] = s * (0.25f / (4096.f * 128.f));
}

extern "C" void kernel_launch(void* const* d_in, const int* in_sizes, int n_in,
                              void* d_out, int out_size) {
    const float* coords = (const float*)d_in[0];
    const int*   li     = (const int*)d_in[1];
    const float* lat    = (const float*)d_in[2];
    const float* emb    = (const float*)d_in[3];
    const float* mW     = (const float*)d_in[4];
    const float* mb     = (const float*)d_in[5];
    const float* W0     = (const float*)d_in[6];
    const float* b0v    = (const float*)d_in[7];
    const float* Wh     = (const float*)d_in[8];
    const float* bh     = (const float*)d_in[9];
    const float* lW     = (const float*)d_in[10];
    const float* lb     = (const float*)d_in[11];
    float* out = (float*)d_out;

    const int MLP_SMEM = 108544;   // X fp16 (67584) + 2 W stages (2*20480)
    cudaFuncSetAttribute(k_mlp16, cudaFuncAttributeMaxDynamicSharedMemorySize, MLP_SMEM);
    cudaFuncSetAttribute(k_betas, cudaFuncAttributeMaxDynamicSharedMemorySize, 66048);

    k_e2<<<32, 256>>>(emb);
    k_vq<<<256, 256>>>(li, lat, emb);
    k_betas<<<dim3(64, 20), 256, 66048>>>(mW, mb);
    k_wprep<<<1024, 256>>>(W0, Wh);
    k_mlp16<<<2048, 256, MLP_SMEM>>>(coords, b0v, bh, lW, lb, out);
    k_loss<<<1, 1>>>(out, out_size > 786432 ? 1 : 0);
}

// round 10
// speedup vs baseline: 3.8644x; 1.0471x over previous
#include <cuda_runtime.h>
#include <cuda_bf16.h>
#include <cuda_fp16.h>
#include <math.h>

#define BSZ 4096
#define DDIM 128
#define KCODES 2048
#define SSTG 4
#define LHTOT 1280

// -------- device scratch (static; no allocation) --------
__device__ float g_zq[BSZ * DDIM];
__device__ float g_bet[BSZ * LHTOT];
__device__ float g_e2[SSTG * KCODES];
__device__ float g_lpart[256];
__device__ __half g_W0f[256 * 64];
__device__ __half g_Whf[4 * 256 * 256];

typedef unsigned long long ull;

// -------- generic helpers --------
__device__ __forceinline__ float dot4(float4 a, float4 b) {
    return fmaf(a.x, b.x, fmaf(a.y, b.y, fmaf(a.z, b.z, a.w * b.w)));
}
__device__ __forceinline__ float4 f4add(float4 a, float4 b) {
    return make_float4(a.x + b.x, a.y + b.y, a.z + b.z, a.w + b.w);
}
__device__ __forceinline__ float4 f4sub(float4 a, float4 b) {
    return make_float4(a.x - b.x, a.y - b.y, a.z - b.z, a.w - b.w);
}
__device__ __forceinline__ unsigned smem_u32(const void* p) {
    unsigned a;
    asm("{ .reg .u64 t; cvta.to.shared.u64 t, %1; cvt.u32.u64 %0, t; }" : "=r"(a) : "l"(p));
    return a;
}
__device__ __forceinline__ void sts32(unsigned a, unsigned v) {
    asm volatile("st.shared.u32 [%0], %1;" :: "r"(a), "r"(v));
}
__device__ __forceinline__ void sts16(unsigned a, unsigned short v) {
    asm volatile("st.shared.u16 [%0], %1;" :: "r"(a), "h"(v));
}
__device__ __forceinline__ unsigned lds32(unsigned a) {
    unsigned v; asm volatile("ld.shared.b32 %0, [%1];" : "=r"(v) : "r"(a)); return v;
}
__device__ __forceinline__ void ldm4(unsigned* r, unsigned a) {
    asm volatile("ldmatrix.sync.aligned.m8n8.x4.shared.b16 {%0,%1,%2,%3}, [%4];"
        : "=r"(r[0]), "=r"(r[1]), "=r"(r[2]), "=r"(r[3]) : "r"(a));
}
// fp16 mma m16n8k16 -> f32 accum (baseline sm_80)
__device__ __forceinline__ void mma_f16h(float* c, const unsigned* a, unsigned b0, unsigned b1) {
    asm volatile("mma.sync.aligned.m16n8k16.row.col.f32.f16.f16.f32 "
        "{%0,%1,%2,%3},{%4,%5,%6,%7},{%8,%9},{%0,%1,%2,%3};"
        : "+f"(c[0]), "+f"(c[1]), "+f"(c[2]), "+f"(c[3])
        : "r"(a[0]), "r"(a[1]), "r"(a[2]), "r"(a[3]), "r"(b0), "r"(b1));
}
__device__ __forceinline__ void cpa16(unsigned dst, const void* src) {
    asm volatile("cp.async.cg.shared.global [%0], [%1], 16;" :: "r"(dst), "l"(src));
}
#define CPA_COMMIT() asm volatile("cp.async.commit_group;" ::: "memory")
#define CPA_WAIT0()  asm volatile("cp.async.wait_group 0;" ::: "memory")

// accurate fp32 sincos (Cody-Waite; |a| <= 2^9*pi)
__device__ __forceinline__ void sc_f32(float a, float& s, float& c) {
    float n = rintf(a * 0.31830988618f);
    float r = fmaf(-n, 3.140625f, a);
    r = fmaf(-n, 9.67502593994140625e-4f, r);
    r = fmaf(-n, 1.50995788e-7f, r);
    float r2 = r * r;
    float sp = fmaf(r2, fmaf(r2, fmaf(r2, fmaf(r2, fmaf(r2, -2.5052108e-8f, 2.7557319e-6f),
               -1.9841270e-4f), 8.3333333e-3f), -1.6666667e-1f), 1.f);
    float cp = fmaf(r2, fmaf(r2, fmaf(r2, fmaf(r2, fmaf(r2, -2.7557319e-7f, 2.4801587e-5f),
               -1.3888889e-3f), 4.1666667e-2f), -0.5f), 1.f);
    s = r * sp; c = cp;
    if (((int)n) & 1) { s = -s; c = -c; }
}

// ======================================================================
// kernel 1: ||e||^2
// ======================================================================
__global__ void k_e2(const float* __restrict__ emb) {
    int c = blockIdx.x * 256 + threadIdx.x;
    const float4* row = (const float4*)(emb + (size_t)c * DDIM);
    float s = 0.f;
#pragma unroll 8
    for (int i = 0; i < 32; ++i) {
        float4 v = row[i];
        s += v.x * v.x + v.y * v.y + v.z * v.z + v.w * v.w;
    }
    g_e2[c] = s;
}

// ======================================================================
// kernel 2: residual VQ (validated; at FFMA roofline)
// ======================================================================
__global__ __launch_bounds__(256) void k_vq(
    const int* __restrict__ li, const float* __restrict__ lat,
    const float* __restrict__ emb)
{
    __shared__ float4 zc4[16 * 32];
    __shared__ float4 em4[64 * 33];
    __shared__ float  e2s[64];
    __shared__ int    win[16];
    __shared__ float  lred[8];

    const int t = threadIdx.x, bp = t >> 5, cl = t & 31;
    const int b0 = 2 * bp, b1 = b0 + 1;
    const int B0 = blockIdx.x * 16;
    const int l0 = li[B0 + b0], l1 = li[B0 + b1];

    float4 r0 = make_float4(0, 0, 0, 0), r1 = r0, q0 = r0, q1 = r0;
    float loss = 0.f;

    for (int s = 0; s < SSTG; ++s) {
        float4 z0 = *(const float4*)&lat[((size_t)l0 * SSTG + s) * DDIM + cl * 4];
        float4 z1 = *(const float4*)&lat[((size_t)l1 * SSTG + s) * DDIM + cl * 4];
        r0 = f4add(r0, z0); r1 = f4add(r1, z1);
        float4 ca = f4sub(r0, q0), cb = f4sub(r1, q1);
        zc4[b0 * 32 + cl] = ca;
        zc4[b1 * 32 + cl] = cb;

        float bd0 = 3.4e38f, bd1 = 3.4e38f;
        int bi0 = 0, bi1 = 0;

        for (int tb = 0; tb < KCODES; tb += 64) {
            __syncthreads();
#pragma unroll
            for (int i = 0; i < 8; ++i) {
                int lin = t + 256 * i;
                int c = lin >> 5, k4 = lin & 31;
                em4[c * 33 + k4] =
                    *(const float4*)&emb[((size_t)s * KCODES + tb + c) * DDIM + k4 * 4];
            }
            if (t < 64) e2s[t] = g_e2[s * KCODES + tb + t];
            __syncthreads();

            float a00 = 0, a01 = 0, a10 = 0, a11 = 0;
#pragma unroll 4
            for (int k4 = 0; k4 < 32; ++k4) {
                float4 za = zc4[b0 * 32 + k4];
                float4 zb = zc4[b1 * 32 + k4];
                float4 e0 = em4[cl * 33 + k4];
                float4 e1 = em4[(cl + 32) * 33 + k4];
                a00 += dot4(e0, za); a01 += dot4(e0, zb);
                a10 += dot4(e1, za); a11 += dot4(e1, zb);
            }
            float d;
            d = fmaf(-2.f, a00, e2s[cl]);      if (d < bd0) { bd0 = d; bi0 = tb + cl; }
            d = fmaf(-2.f, a10, e2s[cl + 32]); if (d < bd0) { bd0 = d; bi0 = tb + cl + 32; }
            d = fmaf(-2.f, a01, e2s[cl]);      if (d < bd1) { bd1 = d; bi1 = tb + cl; }
            d = fmaf(-2.f, a11, e2s[cl + 32]); if (d < bd1) { bd1 = d; bi1 = tb + cl + 32; }
        }
#pragma unroll
        for (int off = 16; off; off >>= 1) {
            float od = __shfl_down_sync(~0u, bd0, off);
            int   oi = __shfl_down_sync(~0u, bi0, off);
            if (od < bd0 || (od == bd0 && oi < bi0)) { bd0 = od; bi0 = oi; }
            od = __shfl_down_sync(~0u, bd1, off);
            oi = __shfl_down_sync(~0u, bi1, off);
            if (od < bd1 || (od == bd1 && oi < bi1)) { bd1 = od; bi1 = oi; }
        }
        if (cl == 0) { win[b0] = bi0; win[b1] = bi1; }
        __syncthreads();
        int w0 = win[b0], w1 = win[b1];
        float4 e0 = *(const float4*)&emb[((size_t)s * KCODES + w0) * DDIM + cl * 4];
        float4 e1 = *(const float4*)&emb[((size_t)s * KCODES + w1) * DDIM + cl * 4];
        float4 d0 = f4sub(e0, ca), d1 = f4sub(e1, cb);
        loss += dot4(d0, d0) + dot4(d1, d1);
        q0 = f4add(q0, e0); q1 = f4add(q1, e1);
    }
    *(float4*)&g_zq[(size_t)(B0 + b0) * DDIM + cl * 4] = q0;
    *(float4*)&g_zq[(size_t)(B0 + b1) * DDIM + cl * 4] = q1;

#pragma unroll
    for (int off = 16; off; off >>= 1) loss += __shfl_down_sync(~0u, loss, off);
    if (cl == 0) lred[bp] = loss;
    __syncthreads();
    if (t == 0) {
        float s = 0.f;
        for (int i = 0; i < 8; ++i) s += lred[i];
        g_lpart[blockIdx.x] = s;
    }
}

// ======================================================================
// kernel 3: betas (validated)
// ======================================================================
__global__ __launch_bounds__(256) void k_betas(
    const float* __restrict__ mW, const float* __restrict__ mb)
{
    extern __shared__ float sm[];
    float* Zs = sm;
    float* Ws = sm + 64 * 129;
    const int t = threadIdx.x;
    const int i0 = blockIdx.x * 64, r0 = blockIdx.y * 64;
    for (int lin = t; lin < 8192; lin += 256) {
        int r = lin >> 7, k = lin & 127;
        Zs[r * 129 + k] = g_zq[(size_t)(i0 + r) * DDIM + k];
        Ws[r * 129 + k] = mW[(size_t)(r0 + r) * DDIM + k];
    }
    __syncthreads();
    const int ix = t & 15, wy = t >> 4;
    float acc[4][4] = {};
    for (int k = 0; k < 128; ++k) {
        float z[4], w[4];
#pragma unroll
        for (int m = 0; m < 4; ++m) {
            z[m] = Zs[(ix + 16 * m) * 129 + k];
            w[m] = Ws[(wy + 16 * m) * 129 + k];
        }
#pragma unroll
        for (int m = 0; m < 4; ++m)
#pragma unroll
            for (int n = 0; n < 4; ++n) acc[m][n] = fmaf(z[m], w[n], acc[m][n]);
    }
#pragma unroll
    for (int n = 0; n < 4; ++n) {
        float bias = mb[r0 + wy + 16 * n];
#pragma unroll
        for (int m = 0; m < 4; ++m)
            g_bet[(size_t)(i0 + ix + 16 * m) * LHTOT + r0 + wy + 16 * n] = acc[m][n] + bias;
    }
}

// ======================================================================
// kernel 4: fp16 weight conversion (W0 padded 42->64)
// ======================================================================
__global__ void k_wprep(const float* __restrict__ W0, const float* __restrict__ Wh) {
    int i = blockIdx.x * 256 + threadIdx.x;   // grid covers 262144
    if (i < 256 * 64) {
        int n = i >> 6, k = i & 63;
        float w = (k < 42) ? W0[n * 42 + k] : 0.f;
        g_W0f[i] = __float2half_rn(w);
    }
    g_Whf[i] = __float2half_rn(Wh[i]);
}

// ======================================================================
// kernel 5: fp16 HMMA fused MLP, K=64 double-buffered panels, 1 sync/panel
//   2 images/CTA (M=128), N=256. X plane: fp16 [128][264] (stride 528 B).
//   W stages: 2 x fp16 [256 rows][72 halves] (stride 144 B, ldmatrix-clean).
//   17 panels: layer0 = 1 (K=64), layers1..4 = 4 each.
//   All bias+beta prefetched to registers before the mainloop.
// ======================================================================
__global__ __launch_bounds__(256, 1) void k_mlp16(
    const float* __restrict__ coords, const float* __restrict__ b0v,
    const float* __restrict__ bhv, const float* __restrict__ lW,
    const float* __restrict__ lb, float* __restrict__ out)
{
    extern __shared__ char dyn[];
    __shared__ float bbs[512];
    __shared__ float lWs[768];

    const unsigned XB = smem_u32(dyn);
    const unsigned WB = XB + 67584u;

    const int t = threadIdx.x, wid = t >> 5, l = t & 31;
    const int wm = wid & 1, wn = wid >> 1;
    const int blk = blockIdx.x;

    const unsigned aoffb = (unsigned)(wm * 64 + (l & 15)) * 528u + (unsigned)((l >> 4) << 3) * 2u;
    const unsigned boffb = (unsigned)(wn * 64 + ((l >> 4) << 3) + (l & 7)) * 144u
                         + (unsigned)(((l >> 3) & 1) << 4);

    auto issue = [&](int g) {
        const __half* Wg; int rstride, k0;
        if (g == 0) { Wg = g_W0f; rstride = 64; k0 = 0; }
        else {
            int Lw = (g - 1) >> 2;
            Wg = g_Whf + (size_t)Lw * 65536; rstride = 256; k0 = ((g - 1) & 3) * 64;
        }
        const __half* src = Wg + (size_t)t * rstride + k0;
        unsigned dst = WB + (unsigned)(g & 1) * 36864u + (unsigned)t * 144u;
#pragma unroll
        for (int c = 0; c < 8; ++c) cpa16(dst + (unsigned)c * 16u, src + c * 8);
        CPA_COMMIT();
    };

    issue(0);

    // ---- prefetch ALL bias+beta into registers (hides L2 latency fully) ----
    float bbr[5][2];
#pragma unroll
    for (int L = 0; L < 5; ++L) {
        float bias = (L == 0) ? b0v[t] : bhv[(L - 1) * 256 + t];
        bbr[L][0] = bias + g_bet[(size_t)(blk * 2) * LHTOT + L * 256 + t];
        bbr[L][1] = bias + g_bet[(size_t)(blk * 2 + 1) * LHTOT + L * 256 + t];
    }
    for (int i = t; i < 768; i += 256) lWs[i] = lW[i];

    // ---- positional encoding -> X rows (fp16), cols 42..63 zero ----
    if (t < 128) {
        const float* cp = coords + ((size_t)(blk * 2) * 64 + t) * 2;
        float cx = cp[0], cy = cp[1];
        unsigned rowo = XB + (unsigned)t * 528u;
        auto wrf = [&](int k, float v) {
            __half h = __float2half_rn(v);
            sts16(rowo + 2u * (unsigned)k, *(unsigned short*)&h);
        };
        wrf(0, cx); wrf(1, cy);
        float fr = 3.14159274101257324f;
#pragma unroll
        for (int f = 0; f < 10; ++f) {
            float sx, cxv, sy, cyv;
            sc_f32(cx * fr, sx, cxv);
            sc_f32(cy * fr, sy, cyv);
            wrf(2 + f, sx); wrf(12 + f, sy);
            wrf(22 + f, cxv); wrf(32 + f, cyv);
            fr *= 2.f;
        }
#pragma unroll
        for (int k = 42; k < 64; ++k) wrf(k, 0.f);
    }

    float acc[4][8][4];
#pragma unroll
    for (int mt = 0; mt < 4; ++mt)
#pragma unroll
        for (int nc = 0; nc < 8; ++nc)
#pragma unroll
            for (int q = 0; q < 4; ++q) acc[mt][nc][q] = 0.f;

    int L = 0;
#pragma unroll 1
    for (int g = 0; g < 17; ++g) {
        CPA_WAIT0();        // panel g resident
        __syncthreads();    // all warps past panel g-1 mma & X/epilogue writes visible
        if (g + 1 < 17) issue(g + 1);   // overlaps mma(g)

        const unsigned wb = WB + (unsigned)(g & 1) * 36864u;
        const int kb = (g == 0) ? 0 : ((g - 1) & 3) * 64;
#pragma unroll 2
        for (int ks = 0; ks < 4; ++ks) {
            unsigned xc = (unsigned)(kb + ks * 16) * 2u;
            unsigned a[4][4];
#pragma unroll
            for (int mt = 0; mt < 4; ++mt)
                ldm4(a[mt], XB + aoffb + xc + (unsigned)mt * (16u * 528u));
#pragma unroll
            for (int bg = 0; bg < 4; ++bg) {
                unsigned bf[4];
                ldm4(bf, wb + boffb + (unsigned)bg * (16u * 144u) + (unsigned)(ks * 32));
#pragma unroll
                for (int mt = 0; mt < 4; ++mt) {
                    mma_f16h(acc[mt][2 * bg],     a[mt], bf[0], bf[1]);
                    mma_f16h(acc[mt][2 * bg + 1], a[mt], bf[2], bf[3]);
                }
            }
        }

        const bool layerEnd = (g == 0) || ((g - 1) & 3) == 3;
        if (layerEnd) {
            __syncthreads();          // all warps done reading X this layer
            bbs[t] = bbr[L][0];
            bbs[t + 256] = bbr[L][1];
            __syncthreads();
            const float* bb = bbs + wm * 256;
#pragma unroll
            for (int mt = 0; mt < 4; ++mt) {
                unsigned ro0 = XB + (unsigned)(wm * 64 + mt * 16 + (l >> 2)) * 528u;
                unsigned ro1 = ro0 + 8u * 528u;
#pragma unroll
                for (int nc = 0; nc < 8; ++nc) {
                    int cb = wn * 64 + nc * 8 + (l & 3) * 2;
                    float b0f = bb[cb], b1f = bb[cb + 1];
                    float x0 = fmaxf(acc[mt][nc][0] + b0f, 0.f);
                    float x1 = fmaxf(acc[mt][nc][1] + b1f, 0.f);
                    float y0 = fmaxf(acc[mt][nc][2] + b0f, 0.f);
                    float y1 = fmaxf(acc[mt][nc][3] + b1f, 0.f);
                    __half2 h0 = __floats2half2_rn(x0, x1);
                    __half2 h1 = __floats2half2_rn(y0, y1);
                    sts32(ro0 + (unsigned)cb * 2u, *(unsigned*)&h0);
                    sts32(ro1 + (unsigned)cb * 2u, *(unsigned*)&h1);
                    acc[mt][nc][0] = 0.f; acc[mt][nc][1] = 0.f;
                    acc[mt][nc][2] = 0.f; acc[mt][nc][3] = 0.f;
                }
            }
            ++L;
            // next panel's top __syncthreads publishes the new X
        }
    }
    __syncthreads();   // final X visible

    // ---- final linear layer: V=3, fp32 from fp16 plane ----
    if (t < 128) {
        float a0 = 0.f, a1 = 0.f, a2 = 0.f;
        unsigned xr = XB + (unsigned)t * 528u;
#pragma unroll 8
        for (int k2 = 0; k2 < 128; ++k2) {
            unsigned hv = lds32(xr + k2 * 4u);
            __half2 h = *(__half2*)&hv;
            float x0 = __half2float(h.x), x1 = __half2float(h.y);
            int k = 2 * k2;
            a0 = fmaf(x0, lWs[k], fmaf(x1, lWs[k + 1], a0));
            a1 = fmaf(x0, lWs[256 + k], fmaf(x1, lWs[256 + k + 1], a1));
            a2 = fmaf(x0, lWs[512 + k], fmaf(x1, lWs[512 + k + 1], a2));
        }
        size_t ob = ((size_t)blk * 128 + t) * 3;
        out[ob]     = a0 + lb[0];
        out[ob + 1] = a1 + lb[1];
        out[ob + 2] = a2 + lb[2];
    }
}

// ======================================================================
// kernel 6: deterministic loss finalize
// ======================================================================
__global__ void k_loss(float* out, int has) {
    if (!has) return;
    float s = 0.f;
    for (int i = 0; i < 256; ++i) s += g_lpart[i];
    out[786432] = s * (0.25f / (4096.f * 128.f));
}

extern "C" void kernel_launch(void* const* d_in, const int* in_sizes, int n_in,
                              void* d_out, int out_size) {
    const float* coords = (const float*)d_in[0];
    const int*   li     = (const int*)d_in[1];
    const float* lat    = (const float*)d_in[2];
    const float* emb    = (const float*)d_in[3];
    const float* mW     = (const float*)d_in[4];
    const float* mb     = (const float*)d_in[5];
    const float* W0     = (const float*)d_in[6];
    const float* b0v    = (const float*)d_in[7];
    const float* Wh     = (const float*)d_in[8];
    const float* bh     = (const float*)d_in[9];
    const float* lW     = (const float*)d_in[10];
    const float* lb     = (const float*)d_in[11];
    float* out = (float*)d_out;

    const int MLP_SMEM = 141312;   // X fp16 (67584) + 2 W stages (2*36864)
    cudaFuncSetAttribute(k_mlp16, cudaFuncAttributeMaxDynamicSharedMemorySize, MLP_SMEM);
    cudaFuncSetAttribute(k_betas, cudaFuncAttributeMaxDynamicSharedMemorySize, 66048);

    k_e2<<<32, 256>>>(emb);
    k_vq<<<256, 256>>>(li, lat, emb);
    k_betas<<<dim3(64, 20), 256, 66048>>>(mW, mb);
    k_wprep<<<1024, 256>>>(W0, Wh);
    k_mlp16<<<2048, 256, MLP_SMEM>>>(coords, b0v, bh, lW, lb, out);
    k_loss<<<1, 1>>>(out, out_size > 786432 ? 1 : 0);
}